// round 1
// baseline (speedup 1.0000x reference)
#include <cuda_runtime.h>
#include <cstdint>
#include <cstddef>

// ---------------- problem constants ----------------
#define BATCH 32
#define C 64          // channels
#define C4 16         // float4 groups per pixel

static __constant__ float c_h0[8] = {
    0.0322231f, -0.01260397f, -0.09921954f, 0.2978578f,
    0.80373875f, 0.49761867f, -0.02963553f, -0.07576571f};
static __constant__ float c_h1[8] = {
    0.07576571f, -0.02963553f, -0.49761867f, 0.80373875f,
   -0.2978578f, -0.09921954f, 0.01260397f, 0.0322231f};
// g = reverse(h)
static __constant__ float c_g0[8] = {
   -0.07576571f, -0.02963553f, 0.49761867f, 0.80373875f,
    0.2978578f, -0.09921954f, -0.01260397f, 0.0322231f};
static __constant__ float c_g1[8] = {
    0.0322231f, 0.01260397f, -0.09921954f, -0.2978578f,
    0.80373875f, -0.49761867f, -0.02963553f, 0.07576571f};

// ---------------- scratch (static __device__, no allocs) ----------------
#define Y1SZ   (BATCH*64*64*64)            // level-1 LL
#define SUBSZ  (BATCH*32*32*64)            // one level-2 subband
#define SUBF4  (SUBSZ/4)
#define WTSZ   (64*64*32*32)               // one weight tensor
#define RESSZ  (BATCH*64*64*64)

static __device__ float g_y1 [Y1SZ];
static __device__ float g_sub[4*SUBSZ];    // ll, lh, hl, hh
static __device__ float g_wt [4*(size_t)WTSZ]; // transposed weights [s][p][i*64+o]
static __device__ float g_mix[4*SUBSZ];    // mixed subbands
static __device__ float g_res[RESSZ];      // level-1 reconstruction

__device__ __forceinline__ float4 f4z() { return make_float4(0.f,0.f,0.f,0.f); }
__device__ __forceinline__ float4 f4fma(float4 a, float s, float4 v) {
    a.x = fmaf(s, v.x, a.x); a.y = fmaf(s, v.y, a.y);
    a.z = fmaf(s, v.z, a.z); a.w = fmaf(s, v.w, a.w);
    return a;
}

// =====================================================================
// Stage 1: level-1 LL DWT.  x(B,128,128,64) -> g_y1(B,64,64,64)
// stride 2, 8-tap separable h0 x h0, pad_lo = 3.
// block: 128 thr = 16 c4-lanes x 8 x_out; grid (8 xtiles, 4 ychunks, B)
// =====================================================================
__global__ __launch_bounds__(128) void k_dwt1(const float* __restrict__ x) {
    const int lane = threadIdx.x & 15;
    const int xo   = (blockIdx.x << 3) + (threadIdx.x >> 4);
    const int y0   = blockIdx.y << 4;      // 16 outputs per chunk (2*y0 % 8 == 0)
    const int b    = blockIdx.z;
    const float4* __restrict__ xin =
        reinterpret_cast<const float4*>(x) + (size_t)b * (128*128*16) + lane;

    float4 H[8];
    // preload input rows 2*y0-3 .. 2*y0+2
    #pragma unroll
    for (int rel = -3; rel <= 2; ++rel) {
        const int r = 2*y0 + rel;
        float4 acc = f4z();
        if (r >= 0) {
            #pragma unroll
            for (int k = 0; k < 8; ++k) {
                const int xi = 2*xo - 3 + k;
                if (xi >= 0 && xi < 128)
                    acc = f4fma(acc, c_h0[k], xin[(r*128 + xi)*16]);
            }
        }
        H[(rel + 8) & 7] = acc;
    }

    float4* __restrict__ yout = reinterpret_cast<float4*>(g_y1)
        + (((size_t)(b*64 + y0))*64 + xo)*16 + lane;

    #pragma unroll
    for (int yy = 0; yy < 16; ++yy) {
        #pragma unroll
        for (int dr = 3; dr <= 4; ++dr) {
            const int rel = 2*yy + dr;
            const int r   = 2*y0 + rel;
            float4 acc = f4z();
            if (r < 128) {
                #pragma unroll
                for (int k = 0; k < 8; ++k) {
                    const int xi = 2*xo - 3 + k;
                    if (xi >= 0 && xi < 128)
                        acc = f4fma(acc, c_h0[k], xin[(r*128 + xi)*16]);
                }
            }
            H[rel & 7] = acc;
        }
        float4 acc = f4z();
        #pragma unroll
        for (int k = 0; k < 8; ++k)
            acc = f4fma(acc, c_h0[k], H[(2*yy - 3 + k + 8) & 7]);
        yout[(size_t)yy * (64*16)] = acc;
    }
}

// =====================================================================
// Stage 2: level-2 DWT, all 4 subbands fused.
// g_y1(B,64,64,64) -> g_sub[4](B,32,32,64). pad_lo = 3.
// block: 128 thr = 16 lanes x 8 x_out; grid (4 xtiles, 4 ychunks(8), B)
// =====================================================================
__global__ __launch_bounds__(128) void k_dwt2() {
    const int lane = threadIdx.x & 15;
    const int xo   = (blockIdx.x << 3) + (threadIdx.x >> 4);  // 0..31
    const int y0   = blockIdx.y << 3;                         // 8 per chunk
    const int b    = blockIdx.z;
    const float4* __restrict__ in =
        reinterpret_cast<const float4*>(g_y1) + (size_t)b * (64*64*16) + lane;

    float4 H0[8], H1[8];
    #pragma unroll
    for (int rel = -3; rel <= 2; ++rel) {
        const int r = 2*y0 + rel;
        float4 a0 = f4z(), a1 = f4z();
        if (r >= 0) {
            #pragma unroll
            for (int k = 0; k < 8; ++k) {
                const int xi = 2*xo - 3 + k;
                if (xi >= 0 && xi < 64) {
                    const float4 v = in[(r*64 + xi)*16];
                    a0 = f4fma(a0, c_h0[k], v);
                    a1 = f4fma(a1, c_h1[k], v);
                }
            }
        }
        H0[(rel + 8) & 7] = a0;
        H1[(rel + 8) & 7] = a1;
    }

    float4* __restrict__ sub = reinterpret_cast<float4*>(g_sub);

    #pragma unroll
    for (int yy = 0; yy < 8; ++yy) {
        #pragma unroll
        for (int dr = 3; dr <= 4; ++dr) {
            const int rel = 2*yy + dr;
            const int r   = 2*y0 + rel;
            float4 a0 = f4z(), a1 = f4z();
            if (r < 64) {
                #pragma unroll
                for (int k = 0; k < 8; ++k) {
                    const int xi = 2*xo - 3 + k;
                    if (xi >= 0 && xi < 64) {
                        const float4 v = in[(r*64 + xi)*16];
                        a0 = f4fma(a0, c_h0[k], v);
                        a1 = f4fma(a1, c_h1[k], v);
                    }
                }
            }
            H0[rel & 7] = a0;
            H1[rel & 7] = a1;
        }
        float4 ll = f4z(), lh = f4z(), hl = f4z(), hh = f4z();
        #pragma unroll
        for (int k = 0; k < 8; ++k) {
            const float4 p0 = H0[(2*yy - 3 + k + 8) & 7];
            const float4 p1 = H1[(2*yy - 3 + k + 8) & 7];
            const float a = c_h0[k], d = c_h1[k];
            ll = f4fma(ll, a, p0);   // y:h0, x:h0
            lh = f4fma(lh, a, p1);   // y:h0, x:h1
            hl = f4fma(hl, d, p0);   // y:h1, x:h0
            hh = f4fma(hh, d, p1);   // y:h1, x:h1
        }
        const size_t o = (((size_t)(b*32 + y0 + yy))*32 + xo)*16 + lane;
        sub[o + 0*(size_t)SUBF4] = ll;
        sub[o + 1*(size_t)SUBF4] = lh;
        sub[o + 2*(size_t)SUBF4] = hl;
        sub[o + 3*(size_t)SUBF4] = hh;
    }
}

// =====================================================================
// Weight transpose: W[i,o,h,w] (4096 x 1024) -> Wt[p=h*32+w][i*64+o]
// grid (32 ptiles, 128 iotiles, 4 weights), block (32, 8)
// =====================================================================
__global__ __launch_bounds__(256) void k_tw(const float* __restrict__ w1,
                                            const float* __restrict__ w2,
                                            const float* __restrict__ w3,
                                            const float* __restrict__ w4) {
    const float* __restrict__ w =
        (blockIdx.z == 0) ? w1 : (blockIdx.z == 1) ? w2 : (blockIdx.z == 2) ? w3 : w4;
    __shared__ float tile[32][33];
    const int p0 = blockIdx.x * 32;
    const int m0 = blockIdx.y * 32;
    const int tx = threadIdx.x, ty = threadIdx.y;
    #pragma unroll
    for (int j = 0; j < 32; j += 8)
        tile[ty + j][tx] = w[(size_t)(m0 + ty + j)*1024 + p0 + tx];
    __syncthreads();
    float* __restrict__ o = g_wt + (size_t)blockIdx.z * WTSZ;
    #pragma unroll
    for (int j = 0; j < 32; j += 8)
        o[(size_t)(p0 + ty + j)*4096 + m0 + tx] = tile[tx][ty + j];
}

// =====================================================================
// Channel mixing: out[b,h,w,o] = sum_i A[b,h,w,i] * W[i,o,h,w]
// per-position 32x64 @ 64x64 GEMM, f32x2 packed FMA.
// grid (1024 positions, 4 subbands), block 64 = 8 o-chunks x 8 b-groups
// thread tile: 4 b x 8 o
// =====================================================================
__global__ __launch_bounds__(64) void k_mix() {
    const int p = blockIdx.x;
    const int s = blockIdx.y;
    const int h = p >> 5, w = p & 31;
    const float* __restrict__ A = g_sub + (size_t)s * SUBSZ;
    const float* __restrict__ W = g_wt + (size_t)s * WTSZ + (size_t)p * 4096;

    __shared__ float Ws[4096];
    __shared__ float As[32 * 65];

    const int t = threadIdx.x;
    #pragma unroll
    for (int i4 = t; i4 < 1024; i4 += 64)
        reinterpret_cast<float4*>(Ws)[i4] = reinterpret_cast<const float4*>(W)[i4];
    #pragma unroll
    for (int idx = t; idx < 512; idx += 64) {
        const int bb = idx >> 4, i4 = (idx & 15) * 4;
        const float4 v = *reinterpret_cast<const float4*>(
            &A[(((size_t)bb*32 + h)*32 + w)*64 + i4]);
        As[bb*65 + i4 + 0] = v.x;
        As[bb*65 + i4 + 1] = v.y;
        As[bb*65 + i4 + 2] = v.z;
        As[bb*65 + i4 + 3] = v.w;
    }
    __syncthreads();

    const int oc = t & 7;   // o base = oc*8
    const int bg = t >> 3;  // b base = bg*4

    unsigned long long acc[4][4];
    #pragma unroll
    for (int j = 0; j < 4; ++j)
        #pragma unroll
        for (int k = 0; k < 4; ++k) acc[j][k] = 0ull;

    #pragma unroll 4
    for (int i = 0; i < 64; ++i) {
        const unsigned long long* wrow =
            reinterpret_cast<const unsigned long long*>(Ws + i*64 + oc*8);
        unsigned long long w2[4];
        #pragma unroll
        for (int k = 0; k < 4; ++k) w2[k] = wrow[k];
        #pragma unroll
        for (int j = 0; j < 4; ++j) {
            const float a = As[(bg*4 + j)*65 + i];
            const unsigned int ai = __float_as_uint(a);
            unsigned long long a2;
            asm("mov.b64 %0, {%1, %1};" : "=l"(a2) : "r"(ai));
            #pragma unroll
            for (int k = 0; k < 4; ++k)
                asm("fma.rn.f32x2 %0, %1, %2, %0;"
                    : "+l"(acc[j][k]) : "l"(a2), "l"(w2[k]));
        }
    }

    float* __restrict__ out = g_mix + (size_t)s * SUBSZ;
    #pragma unroll
    for (int j = 0; j < 4; ++j) {
        const int bb = bg*4 + j;
        const size_t base = (((size_t)bb*32 + h)*32 + w)*64 + oc*8;
        #pragma unroll
        for (int k = 0; k < 4; ++k)
            *reinterpret_cast<unsigned long long*>(out + base + 2*k) = acc[j][k];
    }
}

// =====================================================================
// Recon level 2 -> 1: res = sum_s iconv(up(mix[s]), g_ys x g_xs)
// ft:(g0,g0) lh:(g0,g1) hl:(g1,g0) hh:(g1,g1); 32x32 -> 64x64, pad_lo=3
// block 128 = 16 lanes x 8 x_out; grid (8 xtiles, 4 ychunks(16), B)
// =====================================================================
__global__ __launch_bounds__(128) void k_rec1() {
    const int lane = threadIdx.x & 15;
    const int xo   = (blockIdx.x << 3) + (threadIdx.x >> 4);  // 0..63
    const int y0   = blockIdx.y << 4;
    const int b    = blockIdx.z;

    const int kx0   = (xo & 1) ^ 1;
    const int vbase = (xo - 2) >> 1;
    float fg0[4], fg1[4];
    int   vj[4];
    bool  vok[4];
    #pragma unroll
    for (int j = 0; j < 4; ++j) {
        const int kx = kx0 + 2*j;
        fg0[j] = c_g0[kx];
        fg1[j] = c_g1[kx];
        vj[j]  = vbase + j;
        vok[j] = (vj[j] >= 0 && vj[j] < 32);
    }

    const float4* __restrict__ m0 = reinterpret_cast<const float4*>(g_mix)
        + (size_t)b * (32*32*16) + lane;
    const float4* __restrict__ m1 = m0 + 1*(size_t)SUBF4;
    const float4* __restrict__ m2 = m0 + 2*(size_t)SUBF4;
    const float4* __restrict__ m3 = m0 + 3*(size_t)SUBF4;

    float4 HP[4], HQ[4];
    const int ub = (y0 - 2) >> 1;  // = 8*blockIdx.y - 1

    #define MKROW1(REL) do {                                                 \
        const int u_ = ub + (REL);                                           \
        float4 P_ = f4z(), Q_ = f4z();                                       \
        if ((unsigned)u_ < 32u) {                                            \
            _Pragma("unroll")                                                \
            for (int j = 0; j < 4; ++j) if (vok[j]) {                        \
                const size_t ix = ((size_t)u_*32 + vj[j])*16;                \
                const float4 aft = m0[ix], alh = m1[ix];                     \
                const float4 ahl = m2[ix], ahh = m3[ix];                     \
                P_ = f4fma(P_, fg0[j], aft); P_ = f4fma(P_, fg1[j], alh);    \
                Q_ = f4fma(Q_, fg0[j], ahl); Q_ = f4fma(Q_, fg1[j], ahh);    \
            }                                                                \
        }                                                                    \
        HP[(REL) & 3] = P_; HQ[(REL) & 3] = Q_;                              \
    } while (0)

    MKROW1(0); MKROW1(1); MKROW1(2); MKROW1(3);

    float4* __restrict__ out = reinterpret_cast<float4*>(g_res)
        + (((size_t)(b*64 + y0))*64 + xo)*16 + lane;

    #pragma unroll
    for (int yy = 0; yy < 16; ++yy) {
        if (yy >= 2 && (yy & 1) == 0) {
            MKROW1(yy/2 + 3);
        }
        float4 acc = f4z();
        const int ky0 = (yy & 1) ^ 1;
        #pragma unroll
        for (int j = 0; j < 4; ++j) {
            const int rel = (yy >> 1) + j;
            const int ky  = ky0 + 2*j;
            acc = f4fma(acc, c_g0[ky], HP[rel & 3]);
            acc = f4fma(acc, c_g1[ky], HQ[rel & 3]);
        }
        out[(size_t)yy * (64*16)] = acc;
    }
    #undef MKROW1
}

// =====================================================================
// Recon level 1 -> 0: out = iconv(up(res), g0 x g0). 64x64 -> 128x128.
// block 128 = 16 lanes x 8 x_out; grid (16 xtiles, 8 ychunks(16), B)
// =====================================================================
__global__ __launch_bounds__(128) void k_rec2(float* __restrict__ outp) {
    const int lane = threadIdx.x & 15;
    const int xo   = (blockIdx.x << 3) + (threadIdx.x >> 4);  // 0..127
    const int y0   = blockIdx.y << 4;
    const int b    = blockIdx.z;

    const int kx0   = (xo & 1) ^ 1;
    const int vbase = (xo - 2) >> 1;
    float fg0[4];
    int   vj[4];
    bool  vok[4];
    #pragma unroll
    for (int j = 0; j < 4; ++j) {
        fg0[j] = c_g0[kx0 + 2*j];
        vj[j]  = vbase + j;
        vok[j] = (vj[j] >= 0 && vj[j] < 64);
    }

    const float4* __restrict__ in = reinterpret_cast<const float4*>(g_res)
        + (size_t)b * (64*64*16) + lane;

    float4 HP[4];
    const int ub = (y0 - 2) >> 1;

    #define MKROW2(REL) do {                                                 \
        const int u_ = ub + (REL);                                           \
        float4 P_ = f4z();                                                   \
        if ((unsigned)u_ < 64u) {                                            \
            _Pragma("unroll")                                                \
            for (int j = 0; j < 4; ++j) if (vok[j])                          \
                P_ = f4fma(P_, fg0[j], in[((size_t)u_*64 + vj[j])*16]);      \
        }                                                                    \
        HP[(REL) & 3] = P_;                                                  \
    } while (0)

    MKROW2(0); MKROW2(1); MKROW2(2); MKROW2(3);

    float4* __restrict__ out = reinterpret_cast<float4*>(outp)
        + (((size_t)(b*128 + y0))*128 + xo)*16 + lane;

    #pragma unroll
    for (int yy = 0; yy < 16; ++yy) {
        if (yy >= 2 && (yy & 1) == 0) {
            MKROW2(yy/2 + 3);
        }
        float4 acc = f4z();
        const int ky0 = (yy & 1) ^ 1;
        #pragma unroll
        for (int j = 0; j < 4; ++j) {
            const int rel = (yy >> 1) + j;
            acc = f4fma(acc, c_g0[ky0 + 2*j], HP[rel & 3]);
        }
        out[(size_t)yy * (128*16)] = acc;
    }
    #undef MKROW2
}

// =====================================================================
extern "C" void kernel_launch(void* const* d_in, const int* in_sizes, int n_in,
                              void* d_out, int out_size) {
    (void)in_sizes; (void)n_in; (void)out_size;
    const float* x  = (const float*)d_in[0];
    const float* w1 = (const float*)d_in[1];
    const float* w2 = (const float*)d_in[2];
    const float* w3 = (const float*)d_in[3];
    const float* w4 = (const float*)d_in[4];
    float* out = (float*)d_out;

    k_dwt1<<<dim3(8, 4, BATCH), 128>>>(x);
    k_dwt2<<<dim3(4, 4, BATCH), 128>>>();
    k_tw  <<<dim3(32, 128, 4), dim3(32, 8)>>>(w1, w2, w3, w4);
    k_mix <<<dim3(1024, 4), 64>>>();
    k_rec1<<<dim3(8, 4, BATCH), 128>>>();
    k_rec2<<<dim3(16, 8, BATCH), 128>>>(out);
}

// round 2
// speedup vs baseline: 1.0961x; 1.0961x over previous
#include <cuda_runtime.h>
#include <cstdint>
#include <cstddef>

// ---------------- problem constants ----------------
#define BATCH 32
#define C 64          // channels
#define C4 16         // float4 groups per pixel

static __constant__ float c_h0[8] = {
    0.0322231f, -0.01260397f, -0.09921954f, 0.2978578f,
    0.80373875f, 0.49761867f, -0.02963553f, -0.07576571f};
static __constant__ float c_h1[8] = {
    0.07576571f, -0.02963553f, -0.49761867f, 0.80373875f,
   -0.2978578f, -0.09921954f, 0.01260397f, 0.0322231f};
// g = reverse(h)
static __constant__ float c_g0[8] = {
   -0.07576571f, -0.02963553f, 0.49761867f, 0.80373875f,
    0.2978578f, -0.09921954f, -0.01260397f, 0.0322231f};
static __constant__ float c_g1[8] = {
    0.0322231f, 0.01260397f, -0.09921954f, -0.2978578f,
    0.80373875f, -0.49761867f, -0.02963553f, 0.07576571f};

// ---------------- scratch (static __device__, no allocs) ----------------
#define Y1SZ   (BATCH*64*64*64)            // level-1 LL
#define SUBSZ  (BATCH*32*32*64)            // one level-2 subband
#define SUBF4  (SUBSZ/4)
#define RESSZ  (BATCH*64*64*64)

static __device__ float g_y1 [Y1SZ];
static __device__ float g_sub[4*SUBSZ];    // ll, lh, hl, hh
static __device__ float g_mix[4*SUBSZ];    // mixed subbands
static __device__ float g_res[RESSZ];      // level-1 reconstruction

__device__ __forceinline__ float4 f4z() { return make_float4(0.f,0.f,0.f,0.f); }
__device__ __forceinline__ float4 f4fma(float4 a, float s, float4 v) {
    a.x = fmaf(s, v.x, a.x); a.y = fmaf(s, v.y, a.y);
    a.z = fmaf(s, v.z, a.z); a.w = fmaf(s, v.w, a.w);
    return a;
}

__device__ __forceinline__ unsigned long long dup2(float a) {
    unsigned long long r;
    asm("mov.b64 %0, {%1, %1};" : "=l"(r) : "f"(a));
    return r;
}
__device__ __forceinline__ unsigned long long pk2(float x, float y) {
    unsigned long long r;
    asm("mov.b64 %0, {%1, %2};" : "=l"(r) : "f"(x), "f"(y));
    return r;
}
__device__ __forceinline__ void unpk2(unsigned long long v, float& lo, float& hi) {
    asm("mov.b64 {%0, %1}, %2;" : "=f"(lo), "=f"(hi) : "l"(v));
}

// =====================================================================
// Stage 1: level-1 LL DWT.  x(B,128,128,64) -> g_y1(B,64,64,64)
// stride 2, 8-tap separable h0 x h0, pad_lo = 3.
// block: 128 thr = 16 c4-lanes x 8 x_out; grid (8 xtiles, 4 ychunks, B)
// =====================================================================
__global__ __launch_bounds__(128) void k_dwt1(const float* __restrict__ x) {
    const int lane = threadIdx.x & 15;
    const int xo   = (blockIdx.x << 3) + (threadIdx.x >> 4);
    const int y0   = blockIdx.y << 4;      // 16 outputs per chunk
    const int b    = blockIdx.z;
    const float4* __restrict__ xin =
        reinterpret_cast<const float4*>(x) + (size_t)b * (128*128*16) + lane;

    float4 H[8];
    #pragma unroll
    for (int rel = -3; rel <= 2; ++rel) {
        const int r = 2*y0 + rel;
        float4 acc = f4z();
        if (r >= 0) {
            #pragma unroll
            for (int k = 0; k < 8; ++k) {
                const int xi = 2*xo - 3 + k;
                if (xi >= 0 && xi < 128)
                    acc = f4fma(acc, c_h0[k], xin[(r*128 + xi)*16]);
            }
        }
        H[(rel + 8) & 7] = acc;
    }

    float4* __restrict__ yout = reinterpret_cast<float4*>(g_y1)
        + (((size_t)(b*64 + y0))*64 + xo)*16 + lane;

    #pragma unroll
    for (int yy = 0; yy < 16; ++yy) {
        #pragma unroll
        for (int dr = 3; dr <= 4; ++dr) {
            const int rel = 2*yy + dr;
            const int r   = 2*y0 + rel;
            float4 acc = f4z();
            if (r < 128) {
                #pragma unroll
                for (int k = 0; k < 8; ++k) {
                    const int xi = 2*xo - 3 + k;
                    if (xi >= 0 && xi < 128)
                        acc = f4fma(acc, c_h0[k], xin[(r*128 + xi)*16]);
                }
            }
            H[rel & 7] = acc;
        }
        float4 acc = f4z();
        #pragma unroll
        for (int k = 0; k < 8; ++k)
            acc = f4fma(acc, c_h0[k], H[(2*yy - 3 + k + 8) & 7]);
        yout[(size_t)yy * (64*16)] = acc;
    }
}

// =====================================================================
// Stage 2: level-2 DWT, all 4 subbands fused.
// g_y1(B,64,64,64) -> g_sub[4](B,32,32,64). pad_lo = 3.
// =====================================================================
__global__ __launch_bounds__(128) void k_dwt2() {
    const int lane = threadIdx.x & 15;
    const int xo   = (blockIdx.x << 3) + (threadIdx.x >> 4);  // 0..31
    const int y0   = blockIdx.y << 3;                         // 8 per chunk
    const int b    = blockIdx.z;
    const float4* __restrict__ in =
        reinterpret_cast<const float4*>(g_y1) + (size_t)b * (64*64*16) + lane;

    float4 H0[8], H1[8];
    #pragma unroll
    for (int rel = -3; rel <= 2; ++rel) {
        const int r = 2*y0 + rel;
        float4 a0 = f4z(), a1 = f4z();
        if (r >= 0) {
            #pragma unroll
            for (int k = 0; k < 8; ++k) {
                const int xi = 2*xo - 3 + k;
                if (xi >= 0 && xi < 64) {
                    const float4 v = in[(r*64 + xi)*16];
                    a0 = f4fma(a0, c_h0[k], v);
                    a1 = f4fma(a1, c_h1[k], v);
                }
            }
        }
        H0[(rel + 8) & 7] = a0;
        H1[(rel + 8) & 7] = a1;
    }

    float4* __restrict__ sub = reinterpret_cast<float4*>(g_sub);

    #pragma unroll
    for (int yy = 0; yy < 8; ++yy) {
        #pragma unroll
        for (int dr = 3; dr <= 4; ++dr) {
            const int rel = 2*yy + dr;
            const int r   = 2*y0 + rel;
            float4 a0 = f4z(), a1 = f4z();
            if (r < 64) {
                #pragma unroll
                for (int k = 0; k < 8; ++k) {
                    const int xi = 2*xo - 3 + k;
                    if (xi >= 0 && xi < 64) {
                        const float4 v = in[(r*64 + xi)*16];
                        a0 = f4fma(a0, c_h0[k], v);
                        a1 = f4fma(a1, c_h1[k], v);
                    }
                }
            }
            H0[rel & 7] = a0;
            H1[rel & 7] = a1;
        }
        float4 ll = f4z(), lh = f4z(), hl = f4z(), hh = f4z();
        #pragma unroll
        for (int k = 0; k < 8; ++k) {
            const float4 p0 = H0[(2*yy - 3 + k + 8) & 7];
            const float4 p1 = H1[(2*yy - 3 + k + 8) & 7];
            const float a = c_h0[k], d = c_h1[k];
            ll = f4fma(ll, a, p0);
            lh = f4fma(lh, a, p1);
            hl = f4fma(hl, d, p0);
            hh = f4fma(hh, d, p1);
        }
        const size_t o = (((size_t)(b*32 + y0 + yy))*32 + xo)*16 + lane;
        sub[o + 0*(size_t)SUBF4] = ll;
        sub[o + 1*(size_t)SUBF4] = lh;
        sub[o + 2*(size_t)SUBF4] = hl;
        sub[o + 3*(size_t)SUBF4] = hh;
    }
}

// =====================================================================
// Fused channel mixing, weights read in native [i,o,h,w] layout (once).
// out[b,h,w,o] = sum_i A[b,h,w,i] * W[i,o,h,w]
// grid (4wt x 2ot, 32 h, 4 s), block 256 = 8 warps (one w each),
// warp lanes = 4 b-groups (b-tile 8) x 8 o-groups (o-tile 4).
// i processed in 4 chunks of 16 through SMEM.
// =====================================================================
__global__ __launch_bounds__(256) void k_mixw(const float* __restrict__ w1,
                                              const float* __restrict__ w2,
                                              const float* __restrict__ w3,
                                              const float* __restrict__ w4) {
    const int s  = blockIdx.z;
    const int h  = blockIdx.y;
    const int wt = blockIdx.x >> 1;
    const int ot = blockIdx.x & 1;
    const int w0 = wt * 8;
    const int o0 = ot * 32;

    const float* __restrict__ Wg =
        (s == 0) ? w1 : (s == 1) ? w2 : (s == 2) ? w3 : w4;
    const float* __restrict__ A = g_sub + (size_t)s * SUBSZ;

    __shared__ float Ws[16*8*32];   // [i16][w8][o32]
    __shared__ float As[8*16*32];   // [w8][i16][b32]

    const int t    = threadIdx.x;
    const int wl   = t >> 5;        // warp id = local w (0..7)
    const int lane = t & 31;
    const int og   = lane & 7;      // o-group: o = o0 + og*4 .. +3
    const int bg   = lane >> 3;     // b-group: b = bg*8 .. +7

    unsigned long long acc[4][4];   // [o-sub j][b-pair p]
    #pragma unroll
    for (int j = 0; j < 4; ++j)
        #pragma unroll
        for (int p = 0; p < 4; ++p) acc[j][p] = 0ull;

    // decode indices for A staging (constant across chunks)
    const int a_b = t & 31;
    const int a_w = t >> 5;

    #pragma unroll 1
    for (int ic = 0; ic < 4; ++ic) {
        const int ib = ic * 16;
        if (ic) __syncthreads();

        // ---- stage W chunk: Ws[i][w][o] = Wg[(ib+i)*64+o0+o][h*32+w0+w]
        #pragma unroll
        for (int r = 0; r < 4; ++r) {
            const int id = t + 256*r;          // 0..1023
            const int wh = id & 1;             // w half (0: w0..3, 1: w4..7)
            const int o  = (id >> 1) & 31;
            const int i  = id >> 6;            // 0..15
            const float4 v = *reinterpret_cast<const float4*>(
                &Wg[((size_t)(ib + i)*64 + o0 + o)*1024 + h*32 + w0 + wh*4]);
            const int base = (i*8 + wh*4)*32 + o;
            Ws[base + 0*32] = v.x;
            Ws[base + 1*32] = v.y;
            Ws[base + 2*32] = v.z;
            Ws[base + 3*32] = v.w;
        }

        // ---- stage A chunk: As[w][i][b] = A[b,h,w0+w,ib+i]
        #pragma unroll
        for (int i4 = 0; i4 < 4; ++i4) {
            const float4 v = *reinterpret_cast<const float4*>(
                &A[((size_t)(a_b*32 + h)*32 + w0 + a_w)*64 + ib + i4*4]);
            const int base = (a_w*16 + i4*4)*32 + a_b;
            As[base + 0*32] = v.x;
            As[base + 1*32] = v.y;
            As[base + 2*32] = v.z;
            As[base + 3*32] = v.w;
        }
        __syncthreads();

        // ---- compute 16 i-steps
        #pragma unroll
        for (int i = 0; i < 16; ++i) {
            const float4 a0 = *reinterpret_cast<const float4*>(
                &As[(wl*16 + i)*32 + bg*8]);
            const float4 a1 = *reinterpret_cast<const float4*>(
                &As[(wl*16 + i)*32 + bg*8 + 4]);
            const float4 wv = *reinterpret_cast<const float4*>(
                &Ws[(i*8 + wl)*32 + og*4]);

            unsigned long long ap[4];
            ap[0] = pk2(a0.x, a0.y);
            ap[1] = pk2(a0.z, a0.w);
            ap[2] = pk2(a1.x, a1.y);
            ap[3] = pk2(a1.z, a1.w);
            unsigned long long wd[4];
            wd[0] = dup2(wv.x);
            wd[1] = dup2(wv.y);
            wd[2] = dup2(wv.z);
            wd[3] = dup2(wv.w);

            #pragma unroll
            for (int j = 0; j < 4; ++j)
                #pragma unroll
                for (int p = 0; p < 4; ++p)
                    asm("fma.rn.f32x2 %0, %1, %2, %0;"
                        : "+l"(acc[j][p]) : "l"(ap[p]), "l"(wd[j]));
        }
    }

    // ---- writeback: b = bg*8 + 2p + e, o = o0 + og*4 + j
    float* __restrict__ out = g_mix + (size_t)s * SUBSZ;
    float af[4][8];   // [j][local b 0..7]
    #pragma unroll
    for (int j = 0; j < 4; ++j)
        #pragma unroll
        for (int p = 0; p < 4; ++p)
            unpk2(acc[j][p], af[j][2*p], af[j][2*p + 1]);

    #pragma unroll
    for (int jb = 0; jb < 8; ++jb) {
        const int b = bg*8 + jb;
        float4 v = make_float4(af[0][jb], af[1][jb], af[2][jb], af[3][jb]);
        *reinterpret_cast<float4*>(
            &out[((size_t)(b*32 + h)*32 + w0 + wl)*64 + o0 + og*4]) = v;
    }
}

// =====================================================================
// Recon level 2 -> 1: res = sum_s iconv(up(mix[s]), g_ys x g_xs)
// =====================================================================
__global__ __launch_bounds__(128) void k_rec1() {
    const int lane = threadIdx.x & 15;
    const int xo   = (blockIdx.x << 3) + (threadIdx.x >> 4);  // 0..63
    const int y0   = blockIdx.y << 4;
    const int b    = blockIdx.z;

    const int kx0   = (xo & 1) ^ 1;
    const int vbase = (xo - 2) >> 1;
    float fg0[4], fg1[4];
    int   vj[4];
    bool  vok[4];
    #pragma unroll
    for (int j = 0; j < 4; ++j) {
        const int kx = kx0 + 2*j;
        fg0[j] = c_g0[kx];
        fg1[j] = c_g1[kx];
        vj[j]  = vbase + j;
        vok[j] = (vj[j] >= 0 && vj[j] < 32);
    }

    const float4* __restrict__ m0 = reinterpret_cast<const float4*>(g_mix)
        + (size_t)b * (32*32*16) + lane;
    const float4* __restrict__ m1 = m0 + 1*(size_t)SUBF4;
    const float4* __restrict__ m2 = m0 + 2*(size_t)SUBF4;
    const float4* __restrict__ m3 = m0 + 3*(size_t)SUBF4;

    float4 HP[4], HQ[4];
    const int ub = (y0 - 2) >> 1;

    #define MKROW1(REL) do {                                                 \
        const int u_ = ub + (REL);                                           \
        float4 P_ = f4z(), Q_ = f4z();                                       \
        if ((unsigned)u_ < 32u) {                                            \
            _Pragma("unroll")                                                \
            for (int j = 0; j < 4; ++j) if (vok[j]) {                        \
                const size_t ix = ((size_t)u_*32 + vj[j])*16;                \
                const float4 aft = m0[ix], alh = m1[ix];                     \
                const float4 ahl = m2[ix], ahh = m3[ix];                     \
                P_ = f4fma(P_, fg0[j], aft); P_ = f4fma(P_, fg1[j], alh);    \
                Q_ = f4fma(Q_, fg0[j], ahl); Q_ = f4fma(Q_, fg1[j], ahh);    \
            }                                                                \
        }                                                                    \
        HP[(REL) & 3] = P_; HQ[(REL) & 3] = Q_;                              \
    } while (0)

    MKROW1(0); MKROW1(1); MKROW1(2); MKROW1(3);

    float4* __restrict__ out = reinterpret_cast<float4*>(g_res)
        + (((size_t)(b*64 + y0))*64 + xo)*16 + lane;

    #pragma unroll
    for (int yy = 0; yy < 16; ++yy) {
        if (yy >= 2 && (yy & 1) == 0) {
            MKROW1(yy/2 + 3);
        }
        float4 acc = f4z();
        const int ky0 = (yy & 1) ^ 1;
        #pragma unroll
        for (int j = 0; j < 4; ++j) {
            const int rel = (yy >> 1) + j;
            const int ky  = ky0 + 2*j;
            acc = f4fma(acc, c_g0[ky], HP[rel & 3]);
            acc = f4fma(acc, c_g1[ky], HQ[rel & 3]);
        }
        out[(size_t)yy * (64*16)] = acc;
    }
    #undef MKROW1
}

// =====================================================================
// Recon level 1 -> 0: out = iconv(up(res), g0 x g0). 64x64 -> 128x128.
// =====================================================================
__global__ __launch_bounds__(128) void k_rec2(float* __restrict__ outp) {
    const int lane = threadIdx.x & 15;
    const int xo   = (blockIdx.x << 3) + (threadIdx.x >> 4);  // 0..127
    const int y0   = blockIdx.y << 4;
    const int b    = blockIdx.z;

    const int kx0   = (xo & 1) ^ 1;
    const int vbase = (xo - 2) >> 1;
    float fg0[4];
    int   vj[4];
    bool  vok[4];
    #pragma unroll
    for (int j = 0; j < 4; ++j) {
        fg0[j] = c_g0[kx0 + 2*j];
        vj[j]  = vbase + j;
        vok[j] = (vj[j] >= 0 && vj[j] < 64);
    }

    const float4* __restrict__ in = reinterpret_cast<const float4*>(g_res)
        + (size_t)b * (64*64*16) + lane;

    float4 HP[4];
    const int ub = (y0 - 2) >> 1;

    #define MKROW2(REL) do {                                                 \
        const int u_ = ub + (REL);                                           \
        float4 P_ = f4z();                                                   \
        if ((unsigned)u_ < 64u) {                                            \
            _Pragma("unroll")                                                \
            for (int j = 0; j < 4; ++j) if (vok[j])                          \
                P_ = f4fma(P_, fg0[j], in[((size_t)u_*64 + vj[j])*16]);      \
        }                                                                    \
        HP[(REL) & 3] = P_;                                                  \
    } while (0)

    MKROW2(0); MKROW2(1); MKROW2(2); MKROW2(3);

    float4* __restrict__ out = reinterpret_cast<float4*>(outp)
        + (((size_t)(b*128 + y0))*128 + xo)*16 + lane;

    #pragma unroll
    for (int yy = 0; yy < 16; ++yy) {
        if (yy >= 2 && (yy & 1) == 0) {
            MKROW2(yy/2 + 3);
        }
        float4 acc = f4z();
        const int ky0 = (yy & 1) ^ 1;
        #pragma unroll
        for (int j = 0; j < 4; ++j) {
            const int rel = (yy >> 1) + j;
            acc = f4fma(acc, c_g0[ky0 + 2*j], HP[rel & 3]);
        }
        out[(size_t)yy * (128*16)] = acc;
    }
    #undef MKROW2
}

// =====================================================================
extern "C" void kernel_launch(void* const* d_in, const int* in_sizes, int n_in,
                              void* d_out, int out_size) {
    (void)in_sizes; (void)n_in; (void)out_size;
    const float* x  = (const float*)d_in[0];
    const float* w1 = (const float*)d_in[1];
    const float* w2 = (const float*)d_in[2];
    const float* w3 = (const float*)d_in[3];
    const float* w4 = (const float*)d_in[4];
    float* out = (float*)d_out;

    k_dwt1<<<dim3(8, 4, BATCH), 128>>>(x);
    k_dwt2<<<dim3(4, 4, BATCH), 128>>>();
    k_mixw<<<dim3(8, 32, 4), 256>>>(w1, w2, w3, w4);
    k_rec1<<<dim3(8, 4, BATCH), 128>>>();
    k_rec2<<<dim3(16, 8, BATCH), 128>>>(out);
}

// round 3
// speedup vs baseline: 1.1387x; 1.0389x over previous
#include <cuda_runtime.h>
#include <cstdint>
#include <cstddef>

// ---------------- problem constants ----------------
#define BATCH 32
#define C 64          // channels
#define C4 16         // float4 groups per pixel

static __constant__ float c_h0[8] = {
    0.0322231f, -0.01260397f, -0.09921954f, 0.2978578f,
    0.80373875f, 0.49761867f, -0.02963553f, -0.07576571f};
static __constant__ float c_h1[8] = {
    0.07576571f, -0.02963553f, -0.49761867f, 0.80373875f,
   -0.2978578f, -0.09921954f, 0.01260397f, 0.0322231f};
// g = reverse(h)
static __constant__ float c_g0[8] = {
   -0.07576571f, -0.02963553f, 0.49761867f, 0.80373875f,
    0.2978578f, -0.09921954f, -0.01260397f, 0.0322231f};
static __constant__ float c_g1[8] = {
    0.0322231f, 0.01260397f, -0.09921954f, -0.2978578f,
    0.80373875f, -0.49761867f, -0.02963553f, 0.07576571f};

// ---------------- scratch (static __device__, no allocs) ----------------
#define Y1SZ   (BATCH*64*64*64)            // level-1 LL
#define SUBSZ  (BATCH*32*32*64)            // one level-2 subband

// padded mix: per (s,b) plane is 36x36 pixels (halo: -1 .. +34), interior (1..32)
#define MIXW   36
#define MIXPIX (MIXW*MIXW)                 // 1296 pixels
#define MIXPLANE (MIXPIX*64)               // floats per (s,b)
#define MIXSUBSTRIDE_F4 (32*MIXPIX*16)     // float4 stride between subbands

// padded res: per b plane is 68x68 pixels (halo: -1 .. +66), interior (1..64)
#define RESW   68
#define RESPIX (RESW*RESW)
#define RESPLANE (RESPIX*64)

static __device__ float g_y1 [Y1SZ];
static __device__ float g_sub[4*SUBSZ];                 // ll, lh, hl, hh
static __device__ float g_mix[4*32*(size_t)MIXPLANE];   // padded, pads stay zero
static __device__ float g_res[32*(size_t)RESPLANE];     // padded, pads stay zero

__device__ __forceinline__ float4 f4z() { return make_float4(0.f,0.f,0.f,0.f); }
__device__ __forceinline__ float4 f4fma(float4 a, float s, float4 v) {
    a.x = fmaf(s, v.x, a.x); a.y = fmaf(s, v.y, a.y);
    a.z = fmaf(s, v.z, a.z); a.w = fmaf(s, v.w, a.w);
    return a;
}

__device__ __forceinline__ unsigned long long dup2(float a) {
    unsigned long long r;
    asm("mov.b64 %0, {%1, %1};" : "=l"(r) : "f"(a));
    return r;
}
__device__ __forceinline__ unsigned long long pk2(float x, float y) {
    unsigned long long r;
    asm("mov.b64 %0, {%1, %2};" : "=l"(r) : "f"(x), "f"(y));
    return r;
}
__device__ __forceinline__ void unpk2(unsigned long long v, float& lo, float& hi) {
    asm("mov.b64 {%0, %1}, %2;" : "=f"(lo), "=f"(hi) : "l"(v));
}

// =====================================================================
// Stage 1: level-1 LL DWT.  x(B,128,128,64) -> g_y1(B,64,64,64)
// =====================================================================
__global__ __launch_bounds__(128) void k_dwt1(const float* __restrict__ x) {
    const int lane = threadIdx.x & 15;
    const int xo   = (blockIdx.x << 3) + (threadIdx.x >> 4);
    const int y0   = blockIdx.y << 4;      // 16 outputs per chunk
    const int b    = blockIdx.z;
    const float4* __restrict__ xin =
        reinterpret_cast<const float4*>(x) + (size_t)b * (128*128*16) + lane;

    float4 H[8];
    #pragma unroll
    for (int rel = -3; rel <= 2; ++rel) {
        const int r = 2*y0 + rel;
        float4 acc = f4z();
        if (r >= 0) {
            #pragma unroll
            for (int k = 0; k < 8; ++k) {
                const int xi = 2*xo - 3 + k;
                if (xi >= 0 && xi < 128)
                    acc = f4fma(acc, c_h0[k], xin[(r*128 + xi)*16]);
            }
        }
        H[(rel + 8) & 7] = acc;
    }

    float4* __restrict__ yout = reinterpret_cast<float4*>(g_y1)
        + (((size_t)(b*64 + y0))*64 + xo)*16 + lane;

    #pragma unroll
    for (int yy = 0; yy < 16; ++yy) {
        #pragma unroll
        for (int dr = 3; dr <= 4; ++dr) {
            const int rel = 2*yy + dr;
            const int r   = 2*y0 + rel;
            float4 acc = f4z();
            if (r < 128) {
                #pragma unroll
                for (int k = 0; k < 8; ++k) {
                    const int xi = 2*xo - 3 + k;
                    if (xi >= 0 && xi < 128)
                        acc = f4fma(acc, c_h0[k], xin[(r*128 + xi)*16]);
                }
            }
            H[rel & 7] = acc;
        }
        float4 acc = f4z();
        #pragma unroll
        for (int k = 0; k < 8; ++k)
            acc = f4fma(acc, c_h0[k], H[(2*yy - 3 + k + 8) & 7]);
        yout[(size_t)yy * (64*16)] = acc;
    }
}

// =====================================================================
// Stage 2: level-2 DWT, all 4 subbands fused. g_y1 -> g_sub
// =====================================================================
__global__ __launch_bounds__(128) void k_dwt2() {
    const int lane = threadIdx.x & 15;
    const int xo   = (blockIdx.x << 3) + (threadIdx.x >> 4);  // 0..31
    const int y0   = blockIdx.y << 3;                         // 8 per chunk
    const int b    = blockIdx.z;
    const float4* __restrict__ in =
        reinterpret_cast<const float4*>(g_y1) + (size_t)b * (64*64*16) + lane;

    float4 H0[8], H1[8];
    #pragma unroll
    for (int rel = -3; rel <= 2; ++rel) {
        const int r = 2*y0 + rel;
        float4 a0 = f4z(), a1 = f4z();
        if (r >= 0) {
            #pragma unroll
            for (int k = 0; k < 8; ++k) {
                const int xi = 2*xo - 3 + k;
                if (xi >= 0 && xi < 64) {
                    const float4 v = in[(r*64 + xi)*16];
                    a0 = f4fma(a0, c_h0[k], v);
                    a1 = f4fma(a1, c_h1[k], v);
                }
            }
        }
        H0[(rel + 8) & 7] = a0;
        H1[(rel + 8) & 7] = a1;
    }

    float4* __restrict__ sub = reinterpret_cast<float4*>(g_sub);

    #pragma unroll
    for (int yy = 0; yy < 8; ++yy) {
        #pragma unroll
        for (int dr = 3; dr <= 4; ++dr) {
            const int rel = 2*yy + dr;
            const int r   = 2*y0 + rel;
            float4 a0 = f4z(), a1 = f4z();
            if (r < 64) {
                #pragma unroll
                for (int k = 0; k < 8; ++k) {
                    const int xi = 2*xo - 3 + k;
                    if (xi >= 0 && xi < 64) {
                        const float4 v = in[(r*64 + xi)*16];
                        a0 = f4fma(a0, c_h0[k], v);
                        a1 = f4fma(a1, c_h1[k], v);
                    }
                }
            }
            H0[rel & 7] = a0;
            H1[rel & 7] = a1;
        }
        float4 ll = f4z(), lh = f4z(), hl = f4z(), hh = f4z();
        #pragma unroll
        for (int k = 0; k < 8; ++k) {
            const float4 p0 = H0[(2*yy - 3 + k + 8) & 7];
            const float4 p1 = H1[(2*yy - 3 + k + 8) & 7];
            const float a = c_h0[k], d = c_h1[k];
            ll = f4fma(ll, a, p0);
            lh = f4fma(lh, a, p1);
            hl = f4fma(hl, d, p0);
            hh = f4fma(hh, d, p1);
        }
        const size_t o = (((size_t)(b*32 + y0 + yy))*32 + xo)*16 + lane;
        sub[o + 0*(size_t)(SUBSZ/4)] = ll;
        sub[o + 1*(size_t)(SUBSZ/4)] = lh;
        sub[o + 2*(size_t)(SUBSZ/4)] = hl;
        sub[o + 3*(size_t)(SUBSZ/4)] = hh;
    }
}

// =====================================================================
// Fused channel mixing, weights read in native [i,o,h,w] layout (once).
// out written into PADDED g_mix layout.
// =====================================================================
__global__ __launch_bounds__(256) void k_mixw(const float* __restrict__ w1,
                                              const float* __restrict__ w2,
                                              const float* __restrict__ w3,
                                              const float* __restrict__ w4) {
    const int s  = blockIdx.z;
    const int h  = blockIdx.y;
    const int wt = blockIdx.x >> 1;
    const int ot = blockIdx.x & 1;
    const int w0 = wt * 8;
    const int o0 = ot * 32;

    const float* __restrict__ Wg =
        (s == 0) ? w1 : (s == 1) ? w2 : (s == 2) ? w3 : w4;
    const float* __restrict__ A = g_sub + (size_t)s * SUBSZ;

    __shared__ float Ws[16*8*32];   // [i16][w8][o32]
    __shared__ float As[8*16*32];   // [w8][i16][b32]

    const int t    = threadIdx.x;
    const int wl   = t >> 5;        // warp id = local w (0..7)
    const int lane = t & 31;
    const int og   = lane & 7;      // o-group: o = o0 + og*4 .. +3
    const int bg   = lane >> 3;     // b-group: b = bg*8 .. +7

    unsigned long long acc[4][4];
    #pragma unroll
    for (int j = 0; j < 4; ++j)
        #pragma unroll
        for (int p = 0; p < 4; ++p) acc[j][p] = 0ull;

    const int a_b = t & 31;
    const int a_w = t >> 5;

    #pragma unroll 1
    for (int ic = 0; ic < 4; ++ic) {
        const int ib = ic * 16;
        if (ic) __syncthreads();

        #pragma unroll
        for (int r = 0; r < 4; ++r) {
            const int id = t + 256*r;
            const int wh = id & 1;
            const int o  = (id >> 1) & 31;
            const int i  = id >> 6;
            const float4 v = *reinterpret_cast<const float4*>(
                &Wg[((size_t)(ib + i)*64 + o0 + o)*1024 + h*32 + w0 + wh*4]);
            const int base = (i*8 + wh*4)*32 + o;
            Ws[base + 0*32] = v.x;
            Ws[base + 1*32] = v.y;
            Ws[base + 2*32] = v.z;
            Ws[base + 3*32] = v.w;
        }

        #pragma unroll
        for (int i4 = 0; i4 < 4; ++i4) {
            const float4 v = *reinterpret_cast<const float4*>(
                &A[((size_t)(a_b*32 + h)*32 + w0 + a_w)*64 + ib + i4*4]);
            const int base = (a_w*16 + i4*4)*32 + a_b;
            As[base + 0*32] = v.x;
            As[base + 1*32] = v.y;
            As[base + 2*32] = v.z;
            As[base + 3*32] = v.w;
        }
        __syncthreads();

        #pragma unroll
        for (int i = 0; i < 16; ++i) {
            const float4 a0 = *reinterpret_cast<const float4*>(
                &As[(wl*16 + i)*32 + bg*8]);
            const float4 a1 = *reinterpret_cast<const float4*>(
                &As[(wl*16 + i)*32 + bg*8 + 4]);
            const float4 wv = *reinterpret_cast<const float4*>(
                &Ws[(i*8 + wl)*32 + og*4]);

            unsigned long long ap[4];
            ap[0] = pk2(a0.x, a0.y);
            ap[1] = pk2(a0.z, a0.w);
            ap[2] = pk2(a1.x, a1.y);
            ap[3] = pk2(a1.z, a1.w);
            unsigned long long wd[4];
            wd[0] = dup2(wv.x);
            wd[1] = dup2(wv.y);
            wd[2] = dup2(wv.z);
            wd[3] = dup2(wv.w);

            #pragma unroll
            for (int j = 0; j < 4; ++j)
                #pragma unroll
                for (int p = 0; p < 4; ++p)
                    asm("fma.rn.f32x2 %0, %1, %2, %0;"
                        : "+l"(acc[j][p]) : "l"(ap[p]), "l"(wd[j]));
        }
    }

    // writeback into padded mix: pixel (h, w0+wl) -> (h+1, w0+wl+1)
    float af[4][8];
    #pragma unroll
    for (int j = 0; j < 4; ++j)
        #pragma unroll
        for (int p = 0; p < 4; ++p)
            unpk2(acc[j][p], af[j][2*p], af[j][2*p + 1]);

    #pragma unroll
    for (int jb = 0; jb < 8; ++jb) {
        const int b = bg*8 + jb;
        float4 v = make_float4(af[0][jb], af[1][jb], af[2][jb], af[3][jb]);
        const size_t px = ((size_t)(s*32 + b)*MIXW + (h + 1))*MIXW + (w0 + wl + 1);
        *reinterpret_cast<float4*>(&g_mix[px*64 + o0 + og*4]) = v;
    }
}

// =====================================================================
// Recon level 2 -> 1 (padded in/out, no bounds predicates).
// block 128 = 16 lanes x 8 x_out; grid (8 xtiles, 8 ychunks(8), B)
// =====================================================================
__global__ __launch_bounds__(128) void k_rec1() {
    const int lane = threadIdx.x & 15;
    const int xo   = (blockIdx.x << 3) + (threadIdx.x >> 4);  // 0..63
    const int y0   = blockIdx.y << 3;                         // 8 per chunk
    const int b    = blockIdx.z;

    const int kx0   = (xo & 1) ^ 1;
    const int vb    = ((xo - 2) >> 1) + 1;   // padded v base (>= 0)
    float fg0[4], fg1[4];
    #pragma unroll
    for (int j = 0; j < 4; ++j) {
        fg0[j] = c_g0[kx0 + 2*j];
        fg1[j] = c_g1[kx0 + 2*j];
    }

    const float4* __restrict__ m0 = reinterpret_cast<const float4*>(g_mix)
        + (size_t)b * (MIXPIX*16) + lane;
    const float4* __restrict__ m1 = m0 + 1*(size_t)MIXSUBSTRIDE_F4;
    const float4* __restrict__ m2 = m0 + 2*(size_t)MIXSUBSTRIDE_F4;
    const float4* __restrict__ m3 = m0 + 3*(size_t)MIXSUBSTRIDE_F4;

    float4 HP[4], HQ[4];
    const int ub = ((y0 - 2) >> 1) + 1;      // padded u base (>= 0)

    #define MKROW1(REL) do {                                                 \
        const size_t rb = ((size_t)(ub + (REL))*MIXW + vb)*16;               \
        float4 P_ = f4z(), Q_ = f4z();                                       \
        _Pragma("unroll")                                                    \
        for (int j = 0; j < 4; ++j) {                                        \
            const size_t ix = rb + (size_t)j*16;                             \
            const float4 aft = m0[ix], alh = m1[ix];                         \
            const float4 ahl = m2[ix], ahh = m3[ix];                         \
            P_ = f4fma(P_, fg0[j], aft); P_ = f4fma(P_, fg1[j], alh);        \
            Q_ = f4fma(Q_, fg0[j], ahl); Q_ = f4fma(Q_, fg1[j], ahh);        \
        }                                                                    \
        HP[(REL) & 3] = P_; HQ[(REL) & 3] = Q_;                              \
    } while (0)

    MKROW1(0); MKROW1(1); MKROW1(2); MKROW1(3);

    float4* __restrict__ out = reinterpret_cast<float4*>(g_res)
        + (((size_t)b*RESW + (y0 + 1))*RESW + (xo + 1))*16 + lane;

    #pragma unroll
    for (int yy = 0; yy < 8; ++yy) {
        if (yy >= 2 && (yy & 1) == 0) {
            MKROW1(yy/2 + 3);
        }
        float4 acc = f4z();
        const int ky0 = (yy & 1) ^ 1;
        #pragma unroll
        for (int j = 0; j < 4; ++j) {
            const int rel = (yy >> 1) + j;
            const int ky  = ky0 + 2*j;
            acc = f4fma(acc, c_g0[ky], HP[rel & 3]);
            acc = f4fma(acc, c_g1[ky], HQ[rel & 3]);
        }
        out[(size_t)yy * (RESW*16)] = acc;
    }
    #undef MKROW1
}

// =====================================================================
// Recon level 1 -> 0 (padded input, no bounds predicates).
// block 128 = 16 lanes x 8 x_out; grid (16 xtiles, 16 ychunks(8), B)
// =====================================================================
__global__ __launch_bounds__(128) void k_rec2(float* __restrict__ outp) {
    const int lane = threadIdx.x & 15;
    const int xo   = (blockIdx.x << 3) + (threadIdx.x >> 4);  // 0..127
    const int y0   = blockIdx.y << 3;
    const int b    = blockIdx.z;

    const int kx0 = (xo & 1) ^ 1;
    const int vb  = ((xo - 2) >> 1) + 1;     // padded v base
    float fg0[4];
    #pragma unroll
    for (int j = 0; j < 4; ++j) fg0[j] = c_g0[kx0 + 2*j];

    const float4* __restrict__ in = reinterpret_cast<const float4*>(g_res)
        + (size_t)b * (RESPIX*16) + lane;

    float4 HP[4];
    const int ub = ((y0 - 2) >> 1) + 1;      // padded u base

    #define MKROW2(REL) do {                                                 \
        const size_t rb = ((size_t)(ub + (REL))*RESW + vb)*16;               \
        float4 P_ = f4z();                                                   \
        _Pragma("unroll")                                                    \
        for (int j = 0; j < 4; ++j)                                          \
            P_ = f4fma(P_, fg0[j], in[rb + (size_t)j*16]);                   \
        HP[(REL) & 3] = P_;                                                  \
    } while (0)

    MKROW2(0); MKROW2(1); MKROW2(2); MKROW2(3);

    float4* __restrict__ out = reinterpret_cast<float4*>(outp)
        + (((size_t)(b*128 + y0))*128 + xo)*16 + lane;

    #pragma unroll
    for (int yy = 0; yy < 8; ++yy) {
        if (yy >= 2 && (yy & 1) == 0) {
            MKROW2(yy/2 + 3);
        }
        float4 acc = f4z();
        const int ky0 = (yy & 1) ^ 1;
        #pragma unroll
        for (int j = 0; j < 4; ++j) {
            const int rel = (yy >> 1) + j;
            acc = f4fma(acc, c_g0[ky0 + 2*j], HP[rel & 3]);
        }
        out[(size_t)yy * (128*16)] = acc;
    }
    #undef MKROW2
}

// =====================================================================
extern "C" void kernel_launch(void* const* d_in, const int* in_sizes, int n_in,
                              void* d_out, int out_size) {
    (void)in_sizes; (void)n_in; (void)out_size;
    const float* x  = (const float*)d_in[0];
    const float* w1 = (const float*)d_in[1];
    const float* w2 = (const float*)d_in[2];
    const float* w3 = (const float*)d_in[3];
    const float* w4 = (const float*)d_in[4];
    float* out = (float*)d_out;

    k_dwt1<<<dim3(8, 4, BATCH), 128>>>(x);
    k_dwt2<<<dim3(4, 4, BATCH), 128>>>();
    k_mixw<<<dim3(8, 32, 4), 256>>>(w1, w2, w3, w4);
    k_rec1<<<dim3(8, 8, BATCH), 128>>>();
    k_rec2<<<dim3(16, 16, BATCH), 128>>>(out);
}

// round 4
// speedup vs baseline: 1.2212x; 1.0725x over previous
#include <cuda_runtime.h>
#include <cstdint>
#include <cstddef>

// ---------------- problem constants ----------------
#define BATCH 32
#define C 64          // channels
#define C4 16         // float4 groups per pixel

static __constant__ float c_h0[8] = {
    0.0322231f, -0.01260397f, -0.09921954f, 0.2978578f,
    0.80373875f, 0.49761867f, -0.02963553f, -0.07576571f};
static __constant__ float c_h1[8] = {
    0.07576571f, -0.02963553f, -0.49761867f, 0.80373875f,
   -0.2978578f, -0.09921954f, 0.01260397f, 0.0322231f};
// g = reverse(h)
static __constant__ float c_g0[8] = {
   -0.07576571f, -0.02963553f, 0.49761867f, 0.80373875f,
    0.2978578f, -0.09921954f, -0.01260397f, 0.0322231f};
static __constant__ float c_g1[8] = {
    0.0322231f, 0.01260397f, -0.09921954f, -0.2978578f,
    0.80373875f, -0.49761867f, -0.02963553f, 0.07576571f};

// ---------------- scratch (static __device__, no allocs) ----------------
#define Y1SZ   (BATCH*64*64*64)            // level-1 LL
#define SUBSZ  (BATCH*32*32*64)            // one level-2 subband

// padded mix: per (s,b) plane is 36x36 pixels (halo: -1 .. +34), interior (1..32)
#define MIXW   36
#define MIXPIX (MIXW*MIXW)
#define MIXPLANE (MIXPIX*64)
#define MIXSUBSTRIDE_F4 (32*MIXPIX*16)

// padded res: per b plane is 68x68 pixels (halo: -1 .. +66), interior (1..64)
#define RESW   68
#define RESPIX (RESW*RESW)
#define RESPLANE (RESPIX*64)

static __device__ float g_y1 [Y1SZ];
static __device__ float g_sub[4*SUBSZ];                 // ll, lh, hl, hh
static __device__ float g_mix[4*32*(size_t)MIXPLANE];   // padded, pads stay zero
static __device__ float g_res[32*(size_t)RESPLANE];     // padded, pads stay zero

__device__ __forceinline__ float4 f4z() { return make_float4(0.f,0.f,0.f,0.f); }
__device__ __forceinline__ float4 f4fma(float4 a, float s, float4 v) {
    a.x = fmaf(s, v.x, a.x); a.y = fmaf(s, v.y, a.y);
    a.z = fmaf(s, v.z, a.z); a.w = fmaf(s, v.w, a.w);
    return a;
}

__device__ __forceinline__ unsigned long long dup2(float a) {
    unsigned long long r;
    asm("mov.b64 %0, {%1, %1};" : "=l"(r) : "f"(a));
    return r;
}
__device__ __forceinline__ unsigned long long pk2(float x, float y) {
    unsigned long long r;
    asm("mov.b64 %0, {%1, %2};" : "=l"(r) : "f"(x), "f"(y));
    return r;
}
__device__ __forceinline__ void unpk2(unsigned long long v, float& lo, float& hi) {
    asm("mov.b64 {%0, %1}, %2;" : "=f"(lo), "=f"(hi) : "l"(v));
}

// =====================================================================
// Stage 1: level-1 LL DWT.  x(B,128,128,64) -> g_y1(B,64,64,64)
// =====================================================================
__global__ __launch_bounds__(128) void k_dwt1(const float* __restrict__ x) {
    const int lane = threadIdx.x & 15;
    const int xo   = (blockIdx.x << 3) + (threadIdx.x >> 4);
    const int y0   = blockIdx.y << 4;
    const int b    = blockIdx.z;
    const float4* __restrict__ xin =
        reinterpret_cast<const float4*>(x) + (size_t)b * (128*128*16) + lane;

    float4 H[8];
    #pragma unroll
    for (int rel = -3; rel <= 2; ++rel) {
        const int r = 2*y0 + rel;
        float4 acc = f4z();
        if (r >= 0) {
            #pragma unroll
            for (int k = 0; k < 8; ++k) {
                const int xi = 2*xo - 3 + k;
                if (xi >= 0 && xi < 128)
                    acc = f4fma(acc, c_h0[k], xin[(r*128 + xi)*16]);
            }
        }
        H[(rel + 8) & 7] = acc;
    }

    float4* __restrict__ yout = reinterpret_cast<float4*>(g_y1)
        + (((size_t)(b*64 + y0))*64 + xo)*16 + lane;

    #pragma unroll
    for (int yy = 0; yy < 16; ++yy) {
        #pragma unroll
        for (int dr = 3; dr <= 4; ++dr) {
            const int rel = 2*yy + dr;
            const int r   = 2*y0 + rel;
            float4 acc = f4z();
            if (r < 128) {
                #pragma unroll
                for (int k = 0; k < 8; ++k) {
                    const int xi = 2*xo - 3 + k;
                    if (xi >= 0 && xi < 128)
                        acc = f4fma(acc, c_h0[k], xin[(r*128 + xi)*16]);
                }
            }
            H[rel & 7] = acc;
        }
        float4 acc = f4z();
        #pragma unroll
        for (int k = 0; k < 8; ++k)
            acc = f4fma(acc, c_h0[k], H[(2*yy - 3 + k + 8) & 7]);
        yout[(size_t)yy * (64*16)] = acc;
    }
}

// =====================================================================
// Stage 2: level-2 DWT, all 4 subbands fused. g_y1 -> g_sub
// =====================================================================
__global__ __launch_bounds__(128) void k_dwt2() {
    const int lane = threadIdx.x & 15;
    const int xo   = (blockIdx.x << 3) + (threadIdx.x >> 4);  // 0..31
    const int y0   = blockIdx.y << 3;                         // 8 per chunk
    const int b    = blockIdx.z;
    const float4* __restrict__ in =
        reinterpret_cast<const float4*>(g_y1) + (size_t)b * (64*64*16) + lane;

    float4 H0[8], H1[8];
    #pragma unroll
    for (int rel = -3; rel <= 2; ++rel) {
        const int r = 2*y0 + rel;
        float4 a0 = f4z(), a1 = f4z();
        if (r >= 0) {
            #pragma unroll
            for (int k = 0; k < 8; ++k) {
                const int xi = 2*xo - 3 + k;
                if (xi >= 0 && xi < 64) {
                    const float4 v = in[(r*64 + xi)*16];
                    a0 = f4fma(a0, c_h0[k], v);
                    a1 = f4fma(a1, c_h1[k], v);
                }
            }
        }
        H0[(rel + 8) & 7] = a0;
        H1[(rel + 8) & 7] = a1;
    }

    float4* __restrict__ sub = reinterpret_cast<float4*>(g_sub);

    #pragma unroll
    for (int yy = 0; yy < 8; ++yy) {
        #pragma unroll
        for (int dr = 3; dr <= 4; ++dr) {
            const int rel = 2*yy + dr;
            const int r   = 2*y0 + rel;
            float4 a0 = f4z(), a1 = f4z();
            if (r < 64) {
                #pragma unroll
                for (int k = 0; k < 8; ++k) {
                    const int xi = 2*xo - 3 + k;
                    if (xi >= 0 && xi < 64) {
                        const float4 v = in[(r*64 + xi)*16];
                        a0 = f4fma(a0, c_h0[k], v);
                        a1 = f4fma(a1, c_h1[k], v);
                    }
                }
            }
            H0[rel & 7] = a0;
            H1[rel & 7] = a1;
        }
        float4 ll = f4z(), lh = f4z(), hl = f4z(), hh = f4z();
        #pragma unroll
        for (int k = 0; k < 8; ++k) {
            const float4 p0 = H0[(2*yy - 3 + k + 8) & 7];
            const float4 p1 = H1[(2*yy - 3 + k + 8) & 7];
            const float a = c_h0[k], d = c_h1[k];
            ll = f4fma(ll, a, p0);
            lh = f4fma(lh, a, p1);
            hl = f4fma(hl, d, p0);
            hh = f4fma(hh, d, p1);
        }
        const size_t o = (((size_t)(b*32 + y0 + yy))*32 + xo)*16 + lane;
        sub[o + 0*(size_t)(SUBSZ/4)] = ll;
        sub[o + 1*(size_t)(SUBSZ/4)] = lh;
        sub[o + 2*(size_t)(SUBSZ/4)] = hl;
        sub[o + 3*(size_t)(SUBSZ/4)] = hh;
    }
}

// =====================================================================
// Fused channel mixing, weights read in native [i,o,h,w] layout (once).
// =====================================================================
__global__ __launch_bounds__(256) void k_mixw(const float* __restrict__ w1,
                                              const float* __restrict__ w2,
                                              const float* __restrict__ w3,
                                              const float* __restrict__ w4) {
    const int s  = blockIdx.z;
    const int h  = blockIdx.y;
    const int wt = blockIdx.x >> 1;
    const int ot = blockIdx.x & 1;
    const int w0 = wt * 8;
    const int o0 = ot * 32;

    const float* __restrict__ Wg =
        (s == 0) ? w1 : (s == 1) ? w2 : (s == 2) ? w3 : w4;
    const float* __restrict__ A = g_sub + (size_t)s * SUBSZ;

    __shared__ float Ws[16*8*32];   // [i16][w8][o32]
    __shared__ float As[8*16*32];   // [w8][i16][b32]

    const int t    = threadIdx.x;
    const int wl   = t >> 5;
    const int lane = t & 31;
    const int og   = lane & 7;
    const int bg   = lane >> 3;

    unsigned long long acc[4][4];
    #pragma unroll
    for (int j = 0; j < 4; ++j)
        #pragma unroll
        for (int p = 0; p < 4; ++p) acc[j][p] = 0ull;

    const int a_b = t & 31;
    const int a_w = t >> 5;

    #pragma unroll 1
    for (int ic = 0; ic < 4; ++ic) {
        const int ib = ic * 16;
        if (ic) __syncthreads();

        #pragma unroll
        for (int r = 0; r < 4; ++r) {
            const int id = t + 256*r;
            const int wh = id & 1;
            const int o  = (id >> 1) & 31;
            const int i  = id >> 6;
            const float4 v = *reinterpret_cast<const float4*>(
                &Wg[((size_t)(ib + i)*64 + o0 + o)*1024 + h*32 + w0 + wh*4]);
            const int base = (i*8 + wh*4)*32 + o;
            Ws[base + 0*32] = v.x;
            Ws[base + 1*32] = v.y;
            Ws[base + 2*32] = v.z;
            Ws[base + 3*32] = v.w;
        }

        #pragma unroll
        for (int i4 = 0; i4 < 4; ++i4) {
            const float4 v = *reinterpret_cast<const float4*>(
                &A[((size_t)(a_b*32 + h)*32 + w0 + a_w)*64 + ib + i4*4]);
            const int base = (a_w*16 + i4*4)*32 + a_b;
            As[base + 0*32] = v.x;
            As[base + 1*32] = v.y;
            As[base + 2*32] = v.z;
            As[base + 3*32] = v.w;
        }
        __syncthreads();

        #pragma unroll
        for (int i = 0; i < 16; ++i) {
            const float4 a0 = *reinterpret_cast<const float4*>(
                &As[(wl*16 + i)*32 + bg*8]);
            const float4 a1 = *reinterpret_cast<const float4*>(
                &As[(wl*16 + i)*32 + bg*8 + 4]);
            const float4 wv = *reinterpret_cast<const float4*>(
                &Ws[(i*8 + wl)*32 + og*4]);

            unsigned long long ap[4];
            ap[0] = pk2(a0.x, a0.y);
            ap[1] = pk2(a0.z, a0.w);
            ap[2] = pk2(a1.x, a1.y);
            ap[3] = pk2(a1.z, a1.w);
            unsigned long long wd[4];
            wd[0] = dup2(wv.x);
            wd[1] = dup2(wv.y);
            wd[2] = dup2(wv.z);
            wd[3] = dup2(wv.w);

            #pragma unroll
            for (int j = 0; j < 4; ++j)
                #pragma unroll
                for (int p = 0; p < 4; ++p)
                    asm("fma.rn.f32x2 %0, %1, %2, %0;"
                        : "+l"(acc[j][p]) : "l"(ap[p]), "l"(wd[j]));
        }
    }

    float af[4][8];
    #pragma unroll
    for (int j = 0; j < 4; ++j)
        #pragma unroll
        for (int p = 0; p < 4; ++p)
            unpk2(acc[j][p], af[j][2*p], af[j][2*p + 1]);

    #pragma unroll
    for (int jb = 0; jb < 8; ++jb) {
        const int b = bg*8 + jb;
        float4 v = make_float4(af[0][jb], af[1][jb], af[2][jb], af[3][jb]);
        const size_t px = ((size_t)(s*32 + b)*MIXW + (h + 1))*MIXW + (w0 + wl + 1);
        *reinterpret_cast<float4*>(&g_mix[px*64 + o0 + og*4]) = v;
    }
}

// =====================================================================
// Recon level 2 -> 1 (padded, polyphase-paired: each thread does an
// even/odd xo pair sharing all loads).
// block 128 = 16 lanes x 8 xo-pairs; grid (4 xtiles, 8 ychunks(8), B)
// =====================================================================
__global__ __launch_bounds__(128) void k_rec1() {
    const int lane = threadIdx.x & 15;
    const int xo   = (blockIdx.x << 4) + ((threadIdx.x >> 4) << 1);  // even, 0..62
    const int y0   = blockIdx.y << 3;
    const int b    = blockIdx.z;

    const int vb = xo >> 1;   // padded v base, shared by xo (even) and xo+1
    float fe0[4], fe1[4], fo0[4], fo1[4];
    #pragma unroll
    for (int j = 0; j < 4; ++j) {
        fe0[j] = c_g0[1 + 2*j];  fe1[j] = c_g1[1 + 2*j];   // even xo: kx0=1
        fo0[j] = c_g0[2*j];      fo1[j] = c_g1[2*j];       // odd  xo: kx0=0
    }

    const float4* __restrict__ m0 = reinterpret_cast<const float4*>(g_mix)
        + (size_t)b * (MIXPIX*16) + lane;
    const float4* __restrict__ m1 = m0 + 1*(size_t)MIXSUBSTRIDE_F4;
    const float4* __restrict__ m2 = m0 + 2*(size_t)MIXSUBSTRIDE_F4;
    const float4* __restrict__ m3 = m0 + 3*(size_t)MIXSUBSTRIDE_F4;

    float4 PE[4], QE[4], PO[4], QO[4];
    const int ub = ((y0 - 2) >> 1) + 1;

    #define MKROW1(REL) do {                                                 \
        const size_t rb = ((size_t)(ub + (REL))*MIXW + vb)*16;               \
        float4 pe = f4z(), qe = f4z(), po = f4z(), qo = f4z();               \
        _Pragma("unroll")                                                    \
        for (int j = 0; j < 4; ++j) {                                        \
            const size_t ix = rb + (size_t)j*16;                             \
            const float4 aft = m0[ix], alh = m1[ix];                         \
            const float4 ahl = m2[ix], ahh = m3[ix];                         \
            pe = f4fma(pe, fe0[j], aft); pe = f4fma(pe, fe1[j], alh);        \
            qe = f4fma(qe, fe0[j], ahl); qe = f4fma(qe, fe1[j], ahh);        \
            po = f4fma(po, fo0[j], aft); po = f4fma(po, fo1[j], alh);        \
            qo = f4fma(qo, fo0[j], ahl); qo = f4fma(qo, fo1[j], ahh);        \
        }                                                                    \
        PE[(REL) & 3] = pe; QE[(REL) & 3] = qe;                              \
        PO[(REL) & 3] = po; QO[(REL) & 3] = qo;                              \
    } while (0)

    MKROW1(0); MKROW1(1); MKROW1(2); MKROW1(3);

    float4* __restrict__ out = reinterpret_cast<float4*>(g_res)
        + (((size_t)b*RESW + (y0 + 1))*RESW + (xo + 1))*16 + lane;

    #pragma unroll
    for (int yy = 0; yy < 8; ++yy) {
        if (yy >= 2 && (yy & 1) == 0) {
            MKROW1(yy/2 + 3);
        }
        float4 ae = f4z(), ao = f4z();
        const int ky0 = (yy & 1) ^ 1;
        #pragma unroll
        for (int j = 0; j < 4; ++j) {
            const int r  = ((yy >> 1) + j) & 3;
            const float cy0 = c_g0[ky0 + 2*j];
            const float cy1 = c_g1[ky0 + 2*j];
            ae = f4fma(ae, cy0, PE[r]); ae = f4fma(ae, cy1, QE[r]);
            ao = f4fma(ao, cy0, PO[r]); ao = f4fma(ao, cy1, QO[r]);
        }
        out[(size_t)yy * (RESW*16)]      = ae;
        out[(size_t)yy * (RESW*16) + 16] = ao;
    }
    #undef MKROW1
}

// =====================================================================
// Recon level 1 -> 0 (padded input, polyphase-paired xo).
// block 128 = 16 lanes x 8 xo-pairs; grid (8 xtiles, 16 ychunks(8), B)
// =====================================================================
__global__ __launch_bounds__(128) void k_rec2(float* __restrict__ outp) {
    const int lane = threadIdx.x & 15;
    const int xo   = (blockIdx.x << 4) + ((threadIdx.x >> 4) << 1);  // even, 0..126
    const int y0   = blockIdx.y << 3;
    const int b    = blockIdx.z;

    const int vb = xo >> 1;
    float fe0[4], fo0[4];
    #pragma unroll
    for (int j = 0; j < 4; ++j) {
        fe0[j] = c_g0[1 + 2*j];
        fo0[j] = c_g0[2*j];
    }

    const float4* __restrict__ in = reinterpret_cast<const float4*>(g_res)
        + (size_t)b * (RESPIX*16) + lane;

    float4 PE[4], PO[4];
    const int ub = ((y0 - 2) >> 1) + 1;

    #define MKROW2(REL) do {                                                 \
        const size_t rb = ((size_t)(ub + (REL))*RESW + vb)*16;               \
        float4 pe = f4z(), po = f4z();                                       \
        _Pragma("unroll")                                                    \
        for (int j = 0; j < 4; ++j) {                                        \
            const float4 v = in[rb + (size_t)j*16];                          \
            pe = f4fma(pe, fe0[j], v);                                       \
            po = f4fma(po, fo0[j], v);                                       \
        }                                                                    \
        PE[(REL) & 3] = pe; PO[(REL) & 3] = po;                              \
    } while (0)

    MKROW2(0); MKROW2(1); MKROW2(2); MKROW2(3);

    float4* __restrict__ out = reinterpret_cast<float4*>(outp)
        + (((size_t)(b*128 + y0))*128 + xo)*16 + lane;

    #pragma unroll
    for (int yy = 0; yy < 8; ++yy) {
        if (yy >= 2 && (yy & 1) == 0) {
            MKROW2(yy/2 + 3);
        }
        float4 ae = f4z(), ao = f4z();
        const int ky0 = (yy & 1) ^ 1;
        #pragma unroll
        for (int j = 0; j < 4; ++j) {
            const int r = ((yy >> 1) + j) & 3;
            const float cy = c_g0[ky0 + 2*j];
            ae = f4fma(ae, cy, PE[r]);
            ao = f4fma(ao, cy, PO[r]);
        }
        out[(size_t)yy * (128*16)]      = ae;
        out[(size_t)yy * (128*16) + 16] = ao;
    }
    #undef MKROW2
}

// =====================================================================
extern "C" void kernel_launch(void* const* d_in, const int* in_sizes, int n_in,
                              void* d_out, int out_size) {
    (void)in_sizes; (void)n_in; (void)out_size;
    const float* x  = (const float*)d_in[0];
    const float* w1 = (const float*)d_in[1];
    const float* w2 = (const float*)d_in[2];
    const float* w3 = (const float*)d_in[3];
    const float* w4 = (const float*)d_in[4];
    float* out = (float*)d_out;

    k_dwt1<<<dim3(8, 4, BATCH), 128>>>(x);
    k_dwt2<<<dim3(4, 4, BATCH), 128>>>();
    k_mixw<<<dim3(8, 32, 4), 256>>>(w1, w2, w3, w4);
    k_rec1<<<dim3(4, 8, BATCH), 128>>>();
    k_rec2<<<dim3(8, 16, BATCH), 128>>>(out);
}